// round 2
// baseline (speedup 1.0000x reference)
#include <cuda_runtime.h>
#include <cstdint>

// CausalConv1d: out[b,h] = state[b,h,0]*w[h,0] + state[b,h,1]*w[h,1]
//                        + state[b,h,2]*w[h,2] + x[b,h]*w[h,3] + bias[h]
// new_state[b,h,:] = {state[b,h,1], state[b,h,2], x[b,h]}
//
// d_out layout (tuple concatenated): [out (B*H floats)] [new_state (B*H*3 floats)]
//
// HBM-bound: 512 MB total traffic. Each thread handles 4 consecutive (b,h)
// pairs so that the k=3-innermost state tensor is read/written as aligned
// float4s (12 floats per thread = 3x float4).

#define HIDDEN 4096
#define BATCH  4096
#define PAIRS  ((int64_t)BATCH * HIDDEN)          // 16,777,216
#define NTHREADS_TOTAL (PAIRS / 4)                // 4,194,304

__global__ void __launch_bounds__(256, 8)
causal_conv1d_kernel(const float* __restrict__ x,
                     const float* __restrict__ state,
                     const float* __restrict__ weight,   // [HIDDEN,4]
                     const float* __restrict__ bias,     // [HIDDEN]
                     float* __restrict__ out,            // [BATCH,HIDDEN]
                     float* __restrict__ new_state)      // [BATCH,HIDDEN,3]
{
    int64_t t = (int64_t)blockIdx.x * blockDim.x + threadIdx.x;
    if (t >= NTHREADS_TOTAL) return;

    int64_t p0 = t << 2;                 // first of 4 consecutive (b,h) pairs
    int     h0 = (int)(p0 & (HIDDEN - 1)); // 4 consecutive h's (HIDDEN % 4 == 0)

    // ---- loads (all 16B aligned, fully coalesced) ----
    const float4 xv = *reinterpret_cast<const float4*>(x + p0);

    const float4* sp = reinterpret_cast<const float4*>(state + p0 * 3);
    const float4 s0 = sp[0];   // S0..S3
    const float4 s1 = sp[1];   // S4..S7
    const float4 s2 = sp[2];   // S8..S11

    // weight rows are contiguous float4 per h; bias float4 per 4 h's.
    // These hit L1/L2 (80 KB working set, reused by all 4096 batches).
    const float4 w0 = *reinterpret_cast<const float4*>(weight + (int64_t)(h0 + 0) * 4);
    const float4 w1 = *reinterpret_cast<const float4*>(weight + (int64_t)(h0 + 1) * 4);
    const float4 w2 = *reinterpret_cast<const float4*>(weight + (int64_t)(h0 + 2) * 4);
    const float4 w3 = *reinterpret_cast<const float4*>(weight + (int64_t)(h0 + 3) * 4);
    const float4 bv = *reinterpret_cast<const float4*>(bias + h0);

    // ---- compute: pair j uses state floats S[3j],S[3j+1],S[3j+2] and x X[j] ----
    float4 ov;
    ov.x = fmaf(s0.x, w0.x, fmaf(s0.y, w0.y, fmaf(s0.z, w0.z, fmaf(xv.x, w0.w, bv.x))));
    ov.y = fmaf(s0.w, w1.x, fmaf(s1.x, w1.y, fmaf(s1.y, w1.z, fmaf(xv.y, w1.w, bv.y))));
    ov.z = fmaf(s1.z, w2.x, fmaf(s1.w, w2.y, fmaf(s2.x, w2.z, fmaf(xv.z, w2.w, bv.z))));
    ov.w = fmaf(s2.y, w3.x, fmaf(s2.z, w3.y, fmaf(s2.w, w3.z, fmaf(xv.w, w3.w, bv.w))));

    // ---- new_state flat = {S1,S2,X0, S4,S5,X1, S7,S8,X2, S10,S11,X3} ----
    float4 ns0 = make_float4(s0.y, s0.z, xv.x, s1.x);   // S1,S2,X0,S4
    float4 ns1 = make_float4(s1.y, xv.y, s1.w, s2.x);   // S5,X1,S7,S8
    float4 ns2 = make_float4(xv.z, s2.z, s2.w, xv.w);   // X2,S10,S11,X3

    // ---- stores (16B aligned, coalesced) ----
    *reinterpret_cast<float4*>(out + p0) = ov;
    float4* nsp = reinterpret_cast<float4*>(new_state + p0 * 3);
    nsp[0] = ns0;
    nsp[1] = ns1;
    nsp[2] = ns2;
}

extern "C" void kernel_launch(void* const* d_in, const int* in_sizes, int n_in,
                              void* d_out, int out_size)
{
    const float* x      = (const float*)d_in[0];
    const float* state  = (const float*)d_in[1];
    const float* weight = (const float*)d_in[2];
    const float* bias   = (const float*)d_in[3];

    float* out       = (float*)d_out;
    float* new_state = (float*)d_out + PAIRS;   // out is B*H, new_state follows

    const int threads = 256;
    const int blocks  = (int)((NTHREADS_TOTAL + threads - 1) / threads);  // 16384
    causal_conv1d_kernel<<<blocks, threads>>>(x, state, weight, bias, out, new_state);
}